// round 12
// baseline (speedup 1.0000x reference)
#include <cuda_runtime.h>
#include <math.h>

#define BB      32
#define HH      32
#define KVHN    8
#define DD      128
#define SS      2048
#define NCHUNK  32
#define CS      64            // positions per chunk
#define HCS     32            // positions per table pass
#define NT      256           // 8 warps = 8 kv heads
#define SCALE   0.08838834764831845f
#define ROWF    (KVHN*DD)     // floats per slot row (1024)
#define FULLM   0xffffffffu

__device__ float g_acc[(size_t)BB * NCHUNK * HH * DD];  // 16 MB
__device__ float g_m[BB * NCHUNK * HH];
__device__ float g_l[BB * NCHUNK * HH];

__device__ __forceinline__ void l2_prefetch(const void* p) {
    asm volatile("prefetch.global.L2 [%0];" :: "l"(p));
}

// fp32 Cody-Waite reduction into [-pi,pi], then MUFU fast sin/cos.
__device__ __forceinline__ void rope_sincos(float ang, float* s, float* c) {
    const float INV2PI = 0.15915494309189535f;
    const float C1 = 6.28125f;
    const float C2 = 0.0019353071795864769f;
    float n = rintf(ang * INV2PI);
    float r = fmaf(-n, C1, ang);
    r = fmaf(-n, C2, r);
    *s = __sinf(r);
    *c = __cosf(r);
}

__global__ __launch_bounds__(NT, 4) void attn_partial(
    const float* __restrict__ q,
    const float* __restrict__ kc,
    const float* __restrict__ vc,
    const int*   __restrict__ slot_map,
    const int*   __restrict__ pos)
{
    __shared__ float  cos_tab[HCS * 64];          // 8 KB (per pass)
    __shared__ float  sin_tab[HCS * 64];          // 8 KB
    __shared__ float4 q_sm[KVHN * 4 * 2 * 16];    // 16 KB  [head j][lo/hi][c]
    __shared__ float4 sc_sm[KVHN * CS];           // 8 KB   scores -> exp weights
    __shared__ int    slot_sm[CS];
    __shared__ float  pos_sm[CS];
    __shared__ float  invf_sm[64];

    const int b     = blockIdx.y;
    const int chunk = blockIdx.x;
    const int s0    = chunk * CS;
    const int tid   = threadIdx.x;
    const int w     = tid >> 5;            // warp = kv head
    const int l     = tid & 31;
    const int c     = l & 15;              // float4 chunk within row (K phase)
    const int r     = l >> 4;              // row parity within pair
    const int hsel  = c & 3;               // head this lane finalizes

    if (tid < 64) {
        float fi = (float)tid * 0.015625f;
        invf_sm[tid] = expf(-fi * 9.210340371976184f);
    }
    if (tid < CS) {
        slot_sm[tid] = slot_map[b * SS + s0 + tid];
        pos_sm[tid]  = (float)pos[b * SS + s0 + tid];
    }
    __syncthreads();

    // Warm L2 for the first 32 K rows while the prologue runs.
    {
        int sw = tid >> 3;
        int lc = tid & 7;
        int slot = slot_sm[sw];
        if (slot >= 0)
            l2_prefetch(kc + (size_t)slot * ROWF + (w & 3) * 2 * DD + lc * 32);
    }

    // Rope q (4 heads per warp) for dims {4c..4c+3, +64}; fold SCALE; store to shared.
    if (r == 0) {
        float pq = (float)pos[b * SS + SS - 1];
        float cq[4], sq[4];
        #pragma unroll
        for (int i = 0; i < 4; i++)
            rope_sincos(pq * invf_sm[4 * c + i], &sq[i], &cq[i]);
        #pragma unroll
        for (int j = 0; j < 4; j++) {
            const float4* qp = (const float4*)(q + ((size_t)(b * HH + w * 4 + j)) * DD);
            float4 alo = qp[c];
            float4 ahi = qp[c + 16];
            float4 ql, qh;
            ql.x = SCALE * (alo.x * cq[0] - ahi.x * sq[0]);
            qh.x = SCALE * (ahi.x * cq[0] + alo.x * sq[0]);
            ql.y = SCALE * (alo.y * cq[1] - ahi.y * sq[1]);
            qh.y = SCALE * (ahi.y * cq[1] + alo.y * sq[1]);
            ql.z = SCALE * (alo.z * cq[2] - ahi.z * sq[2]);
            qh.z = SCALE * (ahi.z * cq[2] + alo.z * sq[2]);
            ql.w = SCALE * (alo.w * cq[3] - ahi.w * sq[3]);
            qh.w = SCALE * (ahi.w * cq[3] + alo.w * sq[3]);
            q_sm[((w * 4 + j) * 2 + 0) * 16 + c] = ql;
            q_sm[((w * 4 + j) * 2 + 1) * 16 + c] = qh;
        }
    }

    // ---- K phase in two passes of HCS positions; depth-3 SW pipeline ----
    float msel = -1e30f;     // running max for head hsel

    #pragma unroll
    for (int pass = 0; pass < 2; pass++) {
        // Prologue: load this pass's first TWO row pairs before the table build.
        float4 klo, khi, klo1, khi1;
        klo = khi = klo1 = khi1 = make_float4(0.f, 0.f, 0.f, 0.f);
        {
            const int sA = pass * HCS + r;
            const int slotA = slot_sm[sA];
            if (slotA >= 0) {
                const float* kp = kc + (size_t)slotA * ROWF + w * DD + 4 * c;
                klo = *(const float4*)kp;
                khi = *(const float4*)(kp + 64);
            }
            const int slotB = slot_sm[sA + 2];
            if (slotB >= 0) {
                const float* kp = kc + (size_t)slotB * ROWF + w * DD + 4 * c;
                klo1 = *(const float4*)kp;
                khi1 = *(const float4*)(kp + 64);
            }
        }

        // Build cos/sin for positions [pass*HCS, pass*HCS+HCS) — overlaps the loads.
        for (int idx = tid; idx < HCS * 64; idx += NT) {
            int s = idx >> 6;
            int i = idx & 63;
            float sv, cv;
            rope_sincos(pos_sm[pass * HCS + s] * invf_sm[i], &sv, &cv);
            cos_tab[idx] = cv;
            sin_tab[idx] = sv;
        }
        __syncthreads();

        #pragma unroll 4
        for (int sp = 0; sp < HCS; sp += 2) {
            const int sl = sp + r;                 // table-local position
            const int s  = pass * HCS + sl;        // chunk-local position

            // prefetch K row 12 positions ahead into L2
            {
                int sf = s + 12;
                if (sf < CS) {
                    int slotf = slot_sm[sf];
                    if (slotf >= 0) {
                        const float* pp = kc + (size_t)slotf * ROWF + w * DD + 4 * c;
                        l2_prefetch(pp);
                        l2_prefetch(pp + 64);
                    }
                }
            }

            // Preload the pair TWO iterations ahead (depth-3).
            float4 nklo = make_float4(0.f, 0.f, 0.f, 0.f);
            float4 nkhi = make_float4(0.f, 0.f, 0.f, 0.f);
            if (sp + 4 < HCS) {
                const int nslot = slot_sm[s + 4];
                if (nslot >= 0) {
                    const float* np = kc + (size_t)nslot * ROWF + w * DD + 4 * c;
                    nklo = *(const float4*)np;
                    nkhi = *(const float4*)(np + 64);
                }
            }

            const float4 co = *(const float4*)&cos_tab[sl * 64 + 4 * c];
            const float4 si = *(const float4*)&sin_tab[sl * 64 + 4 * c];

            float rlx = klo.x * co.x - khi.x * si.x, rhx = khi.x * co.x + klo.x * si.x;
            float rly = klo.y * co.y - khi.y * si.y, rhy = khi.y * co.y + klo.y * si.y;
            float rlz = klo.z * co.z - khi.z * si.z, rhz = khi.z * co.z + klo.z * si.z;
            float rlw = klo.w * co.w - khi.w * si.w, rhw = khi.w * co.w + klo.w * si.w;

            float p[4];
            #pragma unroll
            for (int j = 0; j < 4; j++) {
                float4 ql = q_sm[((w * 4 + j) * 2 + 0) * 16 + c];
                float4 qh = q_sm[((w * 4 + j) * 2 + 1) * 16 + c];
                p[j] = ql.x * rlx + ql.y * rly + ql.z * rlz + ql.w * rlw
                     + qh.x * rhx + qh.y * rhy + qh.z * rhz + qh.w * rhw;
            }
            // reduce all 4 heads within aligned 4-lane groups (off 1,2)
            #pragma unroll
            for (int j = 0; j < 4; j++) {
                p[j] += __shfl_xor_sync(FULLM, p[j], 1);
                p[j] += __shfl_xor_sync(FULLM, p[j], 2);
            }
            // lane picks its head, finishes over the 4 groups (off 4,8)
            float sv = (hsel == 0) ? p[0] : (hsel == 1) ? p[1] : (hsel == 2) ? p[2] : p[3];
            sv += __shfl_xor_sync(FULLM, sv, 4);
            sv += __shfl_xor_sync(FULLM, sv, 8);
            msel = fmaxf(msel, sv);
            if (c < 4) ((float*)&sc_sm[w * CS + s])[c] = sv;

            klo = klo1; khi = khi1;
            klo1 = nklo; khi1 = nkhi;
        }
        __syncthreads();   // protect table before rebuild / reuse
    }

    // merge the two half-warp maxima; broadcast the 4 head maxima
    msel = fmaxf(msel, __shfl_xor_sync(FULLM, msel, 16));
    const float m0 = __shfl_sync(FULLM, msel, 0);
    const float m1 = __shfl_sync(FULLM, msel, 1);
    const float m2 = __shfl_sync(FULLM, msel, 2);
    const float m3 = __shfl_sync(FULLM, msel, 3);
    __syncwarp();

    // lead-in prefetch of the first 8 V rows
    if (l < 4) {
        #pragma unroll
        for (int s = 0; s < 8; s++) {
            int slot = slot_sm[s];
            if (slot >= 0)
                l2_prefetch(vc + (size_t)slot * ROWF + w * DD + l * 32);
        }
    }

    // ---- scores -> exp weights in shared; l-sums via one butterfly ----
    float l0, l1, l2, l3;
    {
        float4 sca = sc_sm[w * CS + l];
        sca.x = __expf(sca.x - m0); sca.y = __expf(sca.y - m1);
        sca.z = __expf(sca.z - m2); sca.w = __expf(sca.w - m3);
        sc_sm[w * CS + l] = sca;
        float4 scb = sc_sm[w * CS + 32 + l];
        scb.x = __expf(scb.x - m0); scb.y = __expf(scb.y - m1);
        scb.z = __expf(scb.z - m2); scb.w = __expf(scb.w - m3);
        sc_sm[w * CS + 32 + l] = scb;
        l0 = sca.x + scb.x; l1 = sca.y + scb.y;
        l2 = sca.z + scb.z; l3 = sca.w + scb.w;
        #pragma unroll
        for (int off = 16; off > 0; off >>= 1) {
            l0 += __shfl_xor_sync(FULLM, l0, off);
            l1 += __shfl_xor_sync(FULLM, l1, off);
            l2 += __shfl_xor_sync(FULLM, l2, off);
            l3 += __shfl_xor_sync(FULLM, l3, off);
        }
    }
    __syncwarp();

    // ---- V phase: lane owns dims 4l..4l+3; depth-3 SW pipeline ----
    float4 a0 = make_float4(0,0,0,0), a1 = a0, a2 = a0, a3 = a0;

    float4 v4  = make_float4(0.f, 0.f, 0.f, 0.f);
    float4 v4n = make_float4(0.f, 0.f, 0.f, 0.f);
    {
        int slot = slot_sm[0];
        if (slot >= 0)
            v4 = *(const float4*)(vc + (size_t)slot * ROWF + w * DD + 4 * l);
        int slot1 = slot_sm[1];
        if (slot1 >= 0)
            v4n = *(const float4*)(vc + (size_t)slot1 * ROWF + w * DD + 4 * l);
    }

    #pragma unroll 4
    for (int s = 0; s < CS; s++) {
        // prefetch V row 8 ahead
        {
            int sf = s + 8;
            if (sf < CS) {
                int slotf = slot_sm[sf];
                if (slotf >= 0)
                    l2_prefetch(vc + (size_t)slotf * ROWF + w * DD + 4 * l);
            }
        }
        // preload row s+2 before consuming row s
        float4 nnv = make_float4(0.f, 0.f, 0.f, 0.f);
        if (s + 2 < CS) {
            int nslot = slot_sm[s + 2];
            if (nslot >= 0)
                nnv = *(const float4*)(vc + (size_t)nslot * ROWF + w * DD + 4 * l);
        }

        const float4 e = sc_sm[w * CS + s];     // broadcast
        a0.x += e.x * v4.x; a0.y += e.x * v4.y; a0.z += e.x * v4.z; a0.w += e.x * v4.w;
        a1.x += e.y * v4.x; a1.y += e.y * v4.y; a1.z += e.y * v4.z; a1.w += e.y * v4.w;
        a2.x += e.z * v4.x; a2.y += e.z * v4.y; a2.z += e.z * v4.z; a2.w += e.z * v4.w;
        a3.x += e.w * v4.x; a3.y += e.w * v4.y; a3.z += e.w * v4.z; a3.w += e.w * v4.w;

        v4 = v4n; v4n = nnv;
    }

    // ---- Write partials (float4, coalesced) ----
    {
        size_t base = (((size_t)b * NCHUNK + chunk) * HH + w * 4) * DD;
        float4* ga = (float4*)g_acc;
        ga[(base >> 2) + l]            = a0;
        ga[((base + DD) >> 2) + l]     = a1;
        ga[((base + 2 * DD) >> 2) + l] = a2;
        ga[((base + 3 * DD) >> 2) + l] = a3;
    }
    if (l == 0) {
        int mb = (b * NCHUNK + chunk) * HH + w * 4;
        g_m[mb + 0] = m0; g_m[mb + 1] = m1; g_m[mb + 2] = m2; g_m[mb + 3] = m3;
        g_l[mb + 0] = l0; g_l[mb + 1] = l1; g_l[mb + 2] = l2; g_l[mb + 3] = l3;
    }
}

// Combine: one block per (b,h); 8 warps x 4 chunks each; merge via shared.
__global__ __launch_bounds__(256) void attn_combine(float* __restrict__ out)
{
    __shared__ float4 osm[8][32];
    __shared__ float  Lsm[8];

    const int bh = blockIdx.x;
    const int b  = bh >> 5;
    const int h  = bh & 31;
    const int wj = threadIdx.x >> 5;
    const int l  = threadIdx.x & 31;

    float mraw = g_m[(b * NCHUNK + l) * HH + h];
    float M = mraw;
    #pragma unroll
    for (int off = 16; off > 0; off >>= 1)
        M = fmaxf(M, __shfl_xor_sync(FULLM, M, off));

    // precompute the 4 alpha factors so the load loop has full MLP
    float al[4];
    #pragma unroll
    for (int k = 0; k < 4; k++)
        al[k] = __expf(__shfl_sync(FULLM, mraw, wj * 4 + k) - M);

    float L = 0.f;
    float4 o = make_float4(0.f, 0.f, 0.f, 0.f);
    #pragma unroll
    for (int k = 0; k < 4; k++) {
        int idx = (b * NCHUNK + wj * 4 + k) * HH + h;
        L += al[k] * g_l[idx];
        float4 a = ((const float4*)g_acc)[(((size_t)idx * DD) >> 2) + l];
        o.x += al[k] * a.x; o.y += al[k] * a.y;
        o.z += al[k] * a.z; o.w += al[k] * a.w;
    }
    osm[wj][l] = o;
    if (l == 0) Lsm[wj] = L;
    __syncthreads();

    if (wj == 0) {
        float Lt = Lsm[0];
        #pragma unroll
        for (int k = 1; k < 8; k++) {
            float4 t = osm[k][l];
            o.x += t.x; o.y += t.y; o.z += t.z; o.w += t.w;
            Lt += Lsm[k];
        }
        float inv = 1.0f / Lt;
        o.x *= inv; o.y *= inv; o.z *= inv; o.w *= inv;
        ((float4*)out)[(size_t)bh * 32 + l] = o;
    }
}

extern "C" void kernel_launch(void* const* d_in, const int* in_sizes, int n_in,
                              void* d_out, int out_size) {
    const float* query   = (const float*)d_in[0];
    const float* k_cache = (const float*)d_in[1];
    const float* v_cache = (const float*)d_in[2];
    const int*   slots   = (const int*)d_in[3];
    const int*   pos     = (const int*)d_in[4];
    float*       out     = (float*)d_out;

    attn_partial<<<dim3(NCHUNK, BB), NT>>>(query, k_cache, v_cache, slots, pos);
    attn_combine<<<BB * HH, 256>>>(out);
}